// round 2
// baseline (speedup 1.0000x reference)
#include <cuda_runtime.h>
#include <math.h>

#define BB   4
#define CIN  32
#define COUT 64
#define HH   32
#define WW   32
#define KK   3
#define HP   34
#define WP   34

// Scratch (no allocations allowed in kernel_launch): ~2.36MB features + 590KB weights
__device__ float4 g_feat[BB * CIN * HP * WP];          // (cos x, sin x, cos 3x, sin 3x); pad cells hold trig(0)
__device__ float4 g_wx[COUT * CIN * KK * KK];          // (3/4 cw*cpr, 3/4 cw*spr, 1/4 cw*c3pr, 1/4 cw*s3pr)
__device__ float4 g_wy[COUT * CIN * KK * KK];          // same with sw

// ---------------- feature precompute ----------------
// cos^3(x - p) = 3/4 cos(x-p) + 1/4 cos(3(x-p))
//             = 3/4[cx*cp + sx*sp] + 1/4[c3x*c3p + s3x*s3p]
__global__ void feat_kernel(const float* __restrict__ x) {
    int i = blockIdx.x * blockDim.x + threadIdx.x;
    const int total = BB * CIN * HP * WP;
    if (i >= total) return;
    int ww = i % WP;
    int hh = (i / WP) % HP;
    int bc = i / (WP * HP);
    float v = 0.0f;  // pad value is x=0 (cos applied AFTER zero-padding in the reference)
    if (hh >= 1 && hh <= HH && ww >= 1 && ww <= WW)
        v = x[(bc * HH + (hh - 1)) * WW + (ww - 1)];
    float s, c;
    sincosf(v, &s, &c);
    float c3 = c * (4.0f * c * c - 3.0f);   // cos 3x
    float s3 = s * (3.0f - 4.0f * s * s);   // sin 3x
    g_feat[i] = make_float4(c, s, c3, s3);
}

// ---------------- weight folding ----------------
// probe/out_w layout: (CIN, COUT, K, K)  -> idx = ((c*COUT + o)*K + k)*K + l
__global__ void weight_kernel(const float* __restrict__ probe,
                              const float* __restrict__ outw) {
    int i = blockIdx.x * blockDim.x + threadIdx.x;
    const int total = CIN * COUT * KK * KK;
    if (i >= total) return;
    int kl = i % (KK * KK);
    int o  = (i / (KK * KK)) % COUT;
    int c  = i / (KK * KK * COUT);

    float sp, cp, sw, cw;
    sincosf(probe[i], &sp, &cp);
    sincosf(outw[i],  &sw, &cw);
    float c3p = cp * (4.0f * cp * cp - 3.0f);
    float s3p = sp * (3.0f - 4.0f * sp * sp);

    int oidx = (o * CIN + c) * (KK * KK) + kl;   // [o][c][kl] for the conv kernel
    g_wx[oidx] = make_float4(0.75f * cw * cp, 0.75f * cw * sp,
                             0.25f * cw * c3p, 0.25f * cw * s3p);
    g_wy[oidx] = make_float4(0.75f * sw * cp, 0.75f * sw * sp,
                             0.25f * sw * c3p, 0.25f * sw * s3p);
}

// ---------------- main conv ----------------
// Block: 128 threads. Each block: one b, 4 output channels (og*4..+3), 8 rows x 32 cols.
// Each thread: 2 pixels (rows r, r+4) x 4 o-channels x {x,y} -> 16 fp32 accumulators.
// Weights for the 4 o-channels staged in smem (broadcast LDS.128, conflict-free).
#define OG 4
__global__ __launch_bounds__(128, 4) void conv_kernel(float* __restrict__ out) {
    __shared__ float4 s_w[OG * CIN * 9 * 2];   // [o][c][kl][{x,y}]  = 2304 float4 = 36.9KB

    const int b    = blockIdx.z;
    const int og   = blockIdx.y;          // 0..15
    const int tile = blockIdx.x;          // 0..3
    const int tid  = threadIdx.x;
    const int obase = og * OG;

    for (int i = tid; i < OG * CIN * 9 * 2; i += 128) {
        int half = i & 1;
        int idx  = i >> 1;                 // (ol*CIN + c)*9 + kl
        int ol   = idx / (CIN * 9);
        int rest = idx % (CIN * 9);
        int gidx = (obase + ol) * (CIN * 9) + rest;
        s_w[i] = half ? g_wy[gidx] : g_wx[gidx];
    }
    __syncthreads();

    const int col = tid & 31;
    const int r0  = tile * 8 + (tid >> 5);
    const int r1  = r0 + 4;

    float accx0[OG] = {0.f, 0.f, 0.f, 0.f};
    float accy0[OG] = {0.f, 0.f, 0.f, 0.f};
    float accx1[OG] = {0.f, 0.f, 0.f, 0.f};
    float accy1[OG] = {0.f, 0.f, 0.f, 0.f};

    for (int c = 0; c < CIN; c++) {
        const float4* fb = &g_feat[(b * CIN + c) * (HP * WP)];
        #pragma unroll
        for (int k = 0; k < 3; k++) {
            const float4* fr0 = fb + (r0 + k) * WP + col;
            const float4* fr1 = fb + (r1 + k) * WP + col;
            #pragma unroll
            for (int l = 0; l < 3; l++) {
                float4 f0 = fr0[l];
                float4 f1 = fr1[l];
                int wbase = (c * 9 + k * 3 + l) * 2;
                #pragma unroll
                for (int o = 0; o < OG; o++) {
                    float4 wx = s_w[o * (CIN * 9 * 2) + wbase];
                    float4 wy = s_w[o * (CIN * 9 * 2) + wbase + 1];
                    accx0[o] = fmaf(f0.x, wx.x, fmaf(f0.y, wx.y, fmaf(f0.z, wx.z, fmaf(f0.w, wx.w, accx0[o]))));
                    accy0[o] = fmaf(f0.x, wy.x, fmaf(f0.y, wy.y, fmaf(f0.z, wy.z, fmaf(f0.w, wy.w, accy0[o]))));
                    accx1[o] = fmaf(f1.x, wx.x, fmaf(f1.y, wx.y, fmaf(f1.z, wx.z, fmaf(f1.w, wx.w, accx1[o]))));
                    accy1[o] = fmaf(f1.x, wy.x, fmaf(f1.y, wy.y, fmaf(f1.z, wy.z, fmaf(f1.w, wy.w, accy1[o]))));
                }
            }
        }
    }

    #pragma unroll
    for (int o = 0; o < OG; o++) {
        out[((b * COUT + obase + o) * HH + r0) * WW + col] = atan2f(accy0[o], accx0[o]);
        out[((b * COUT + obase + o) * HH + r1) * WW + col] = atan2f(accy1[o], accx1[o]);
    }
}

extern "C" void kernel_launch(void* const* d_in, const int* in_sizes, int n_in,
                              void* d_out, int out_size) {
    const float* x     = (const float*)d_in[0];   // (4,32,32,32)
    const float* probe = (const float*)d_in[1];   // (1,32,64,1,1,3,3)
    const float* outw  = (const float*)d_in[2];   // (1,32,64,1,1,3,3)
    float* out = (float*)d_out;                   // (4,64,32,32)

    {
        const int total = BB * CIN * HP * WP;
        feat_kernel<<<(total + 255) / 256, 256>>>(x);
    }
    {
        const int total = CIN * COUT * KK * KK;
        weight_kernel<<<(total + 255) / 256, 256>>>(probe, outw);
    }
    {
        dim3 grid(4, COUT / OG, BB);   // (row tiles, o-groups, batch)
        conv_kernel<<<grid, 128>>>(out);
    }
    (void)in_sizes; (void)n_in; (void)out_size;
}